// round 7
// baseline (speedup 1.0000x reference)
#include <cuda_runtime.h>
#include <cstdint>

// Problem dims (fixed)
#define HID   1024
#define NBAT  16
#define SEQ   1024
#define MTOT  16384
#define KD    1024            // K depth of every GEMM

// GEMM tiling
#define BKC      128          // K-chunk in int8 elems = 128 B rows
#define NCHUNK   (KD / BKC)   // 8
#define TILE_B   16384        // 128 rows x 128 B
#define STAGE_B  (4 * TILE_B) // A0, A1, B0, B1
#define NSTAGE   3
#define GEMM_SMEM (1024 + NSTAGE * STAGE_B)

// ============================================================================
// PTX helpers (base sm_103 target only)
// ============================================================================
__device__ __forceinline__ uint32_t smem_u32_of(const void* p) {
    uint32_t a;
    asm("{ .reg .u64 t; cvta.to.shared.u64 t, %1; cvt.u32.u64 %0, t; }"
        : "=r"(a) : "l"(p));
    return a;
}
__device__ __forceinline__ void cp16(uint32_t s, const void* g) {
    asm volatile("cp.async.cg.shared.global [%0], [%1], 16;" :: "r"(s), "l"(g));
}
#define CP_COMMIT() asm volatile("cp.async.commit_group;" ::: "memory")
#define CP_WAIT(N)  asm volatile("cp.async.wait_group %0;" :: "n"(N) : "memory")

__device__ __forceinline__ void ldsm4(uint32_t* r, uint32_t addr) {
    asm volatile("ldmatrix.sync.aligned.m8n8.x4.shared.b16 {%0,%1,%2,%3}, [%4];"
        : "=r"(r[0]), "=r"(r[1]), "=r"(r[2]), "=r"(r[3]) : "r"(addr));
}

// IMMA m16n8k32, s32 accumulate, all sign variants
__device__ __forceinline__ void imma_ss(int* c, const uint32_t* a, const uint32_t* b) {
    asm volatile("mma.sync.aligned.m16n8k32.row.col.s32.s8.s8.s32 "
        "{%0,%1,%2,%3}, {%4,%5,%6,%7}, {%8,%9}, {%0,%1,%2,%3};"
        : "+r"(c[0]), "+r"(c[1]), "+r"(c[2]), "+r"(c[3])
        : "r"(a[0]), "r"(a[1]), "r"(a[2]), "r"(a[3]), "r"(b[0]), "r"(b[1]));
}
__device__ __forceinline__ void imma_su(int* c, const uint32_t* a, const uint32_t* b) {
    asm volatile("mma.sync.aligned.m16n8k32.row.col.s32.s8.u8.s32 "
        "{%0,%1,%2,%3}, {%4,%5,%6,%7}, {%8,%9}, {%0,%1,%2,%3};"
        : "+r"(c[0]), "+r"(c[1]), "+r"(c[2]), "+r"(c[3])
        : "r"(a[0]), "r"(a[1]), "r"(a[2]), "r"(a[3]), "r"(b[0]), "r"(b[1]));
}
__device__ __forceinline__ void imma_us(int* c, const uint32_t* a, const uint32_t* b) {
    asm volatile("mma.sync.aligned.m16n8k32.row.col.s32.u8.s8.s32 "
        "{%0,%1,%2,%3}, {%4,%5,%6,%7}, {%8,%9}, {%0,%1,%2,%3};"
        : "+r"(c[0]), "+r"(c[1]), "+r"(c[2]), "+r"(c[3])
        : "r"(a[0]), "r"(a[1]), "r"(a[2]), "r"(a[3]), "r"(b[0]), "r"(b[1]));
}
__device__ __forceinline__ void imma_uu(int* c, const uint32_t* a, const uint32_t* b) {
    asm volatile("mma.sync.aligned.m16n8k32.row.col.s32.u8.u8.s32 "
        "{%0,%1,%2,%3}, {%4,%5,%6,%7}, {%8,%9}, {%0,%1,%2,%3};"
        : "+r"(c[0]), "+r"(c[1]), "+r"(c[2]), "+r"(c[3])
        : "r"(a[0]), "r"(a[1]), "r"(a[2]), "r"(a[3]), "r"(b[0]), "r"(b[1]));
}

__device__ __forceinline__ uint32_t sw128(uint32_t o) { return o ^ ((o >> 3) & 0x70); }

// ============================================================================
// Device global scratch
// ============================================================================
__device__ __align__(16) int8_t  g_Xa0[MTOT * KD];
__device__ __align__(16) uint8_t g_Xa1[MTOT * KD];
__device__             float    g_Xsc[MTOT];
__device__ __align__(16) int8_t  g_Wa0[HID * KD];
__device__ __align__(16) uint8_t g_Wa1[HID * KD];
__device__             float    g_Wsc[HID];
__device__ __align__(16) int8_t  g_Qa0[MTOT * KD];
__device__ __align__(16) uint8_t g_Qa1[MTOT * KD];
__device__             float    g_Qsc[MTOT];
__device__ __align__(16) int8_t  g_Ka0[MTOT * KD];
__device__ __align__(16) uint8_t g_Ka1[MTOT * KD];
__device__             float    g_Ksc[MTOT];
__device__ __align__(16) int8_t  g_Va0[MTOT * KD];   // VT segments, quant row = a*16+z
__device__ __align__(16) uint8_t g_Va1[MTOT * KD];
__device__             float    g_Vsc[MTOT];
__device__ __align__(16) int8_t  g_Pa0[MTOT * KD];
__device__ __align__(16) uint8_t g_Pa1[MTOT * KD];
__device__             float    g_Psc[MTOT];
__device__ __align__(16) float   g_F[MTOT * KD];     // fp32 staging (reused)

// ============================================================================
// Row quantization: fp32 row [1024] -> s8 hi, u8 lo, scale
//   x16 = round(x * 32512 / rowmax);  a0 = x16>>8 (s8);  a1 = x16&255 (u8)
// ============================================================================
__global__ void __launch_bounds__(256)
quant_rows(const float* __restrict__ X, int8_t* __restrict__ A0,
           uint8_t* __restrict__ A1, float* __restrict__ sc)
{
    const int row = blockIdx.x;
    const int t = threadIdx.x;
    const int w = t >> 5, l = t & 31;
    __shared__ float red[8];

    float4 v = *reinterpret_cast<const float4*>(X + (size_t)row * 1024 + t * 4);

    float m = fmaxf(fmaxf(fabsf(v.x), fabsf(v.y)), fmaxf(fabsf(v.z), fabsf(v.w)));
#pragma unroll
    for (int o = 16; o; o >>= 1) m = fmaxf(m, __shfl_xor_sync(0xffffffffu, m, o));
    if (l == 0) red[w] = m;
    __syncthreads();
    float rm = fmaxf(fmaxf(fmaxf(red[0], red[1]), fmaxf(red[2], red[3])),
                     fmaxf(fmaxf(red[4], red[5]), fmaxf(red[6], red[7])));
    rm = fmaxf(rm, 1e-20f);

    const float inv = 32512.0f / rm;
    int x0 = max(-32512, min(32512, __float2int_rn(v.x * inv)));
    int x1 = max(-32512, min(32512, __float2int_rn(v.y * inv)));
    int x2 = max(-32512, min(32512, __float2int_rn(v.z * inv)));
    int x3 = max(-32512, min(32512, __float2int_rn(v.w * inv)));

    uchar4 hi = make_uchar4((uint8_t)(int8_t)(x0 >> 8), (uint8_t)(int8_t)(x1 >> 8),
                            (uint8_t)(int8_t)(x2 >> 8), (uint8_t)(int8_t)(x3 >> 8));
    uchar4 lo = make_uchar4((uint8_t)(x0 & 255), (uint8_t)(x1 & 255),
                            (uint8_t)(x2 & 255), (uint8_t)(x3 & 255));
    *reinterpret_cast<uchar4*>(A0 + (size_t)row * 1024 + t * 4) = hi;
    *reinterpret_cast<uchar4*>(A1 + (size_t)row * 1024 + t * 4) = lo;

    if (t == 0) sc[row] = rm * (1.0f / 32512.0f);
}

// ============================================================================
// Int8-split NT GEMM (EXACT 16-bit fixed-point):
//   C[m][n] = sA[m]*sB[n]*(65536*C00 + 256*Cmid + C11) (+ bias)
//   CTA 128x128, K=1024, 3-stage cp.async, 8 warps (2M x 4N), warp 64x32.
//   4 IMMA m16n8k32 per (tile, k32): ss, su, us, uu.
//   BIAS_MODE: 0 none, 1 per-col bias[n], 2 per-row bias[m]
// ============================================================================
template<int BIAS_MODE>
__global__ void __launch_bounds__(256, 1)
gemm_i8(const int8_t* __restrict__ A0, const uint8_t* __restrict__ A1,
        const float* __restrict__ scA,
        int lda, size_t strA, size_t sScA,
        const int8_t* __restrict__ B0, const uint8_t* __restrict__ B1,
        const float* __restrict__ scB,
        int ldb, size_t strB, size_t sScB, int ldScB,
        const float* __restrict__ bias,
        float* __restrict__ C, int ldc, size_t strC)
{
    extern __shared__ char smem[];
    const int tid  = threadIdx.x;
    const int lane = tid & 31;
    const int wid  = tid >> 5;
    const int wm   = wid >> 2;        // 0..1
    const int wn   = wid & 3;         // 0..3
    const int z    = blockIdx.z;

    const int rowBase = blockIdx.y * 128;
    const int colBase = blockIdx.x * 128;

    const int8_t*  aA0 = A0 + z * strA + (size_t)rowBase * lda;
    const uint8_t* aA1 = A1 + z * strA + (size_t)rowBase * lda;
    const int8_t*  aB0 = B0 + z * strB + (size_t)colBase * ldb;
    const uint8_t* aB1 = B1 + z * strB + (size_t)colBase * ldb;

    const uint32_t raw  = smem_u32_of(smem);
    const uint32_t base = (raw + 1023u) & ~1023u;

    auto load_chunk = [&](int k0, uint32_t stg) {
#pragma unroll
        for (int it = 0; it < 4; ++it) {
            const int slot = tid + it * 256;       // 0..1023
            const int r    = slot >> 3;            // 0..127
            const int seg  = slot & 7;             // 16B segment
            const uint32_t so = sw128((uint32_t)(r * 128 + seg * 16));
            const size_t ga = (size_t)r * lda + k0 + seg * 16;
            const size_t gb = (size_t)r * ldb + k0 + seg * 16;
            cp16(stg + 0 * TILE_B + so, aA0 + ga);
            cp16(stg + 1 * TILE_B + so, aA1 + ga);
            cp16(stg + 2 * TILE_B + so, aB0 + gb);
            cp16(stg + 3 * TILE_B + so, aB1 + gb);
        }
        CP_COMMIT();
    };

    int acc0[4][4][4];   // a0*b0
    int accm[4][4][4];   // a0*b1 + a1*b0
    int acc1[4][4][4];   // a1*b1
#pragma unroll
    for (int mt = 0; mt < 4; ++mt)
#pragma unroll
        for (int nt = 0; nt < 4; ++nt)
#pragma unroll
            for (int e = 0; e < 4; ++e) {
                acc0[mt][nt][e] = 0; accm[mt][nt][e] = 0; acc1[mt][nt][e] = 0;
            }

    load_chunk(0, base + 0 * STAGE_B);
    load_chunk(BKC, base + 1 * STAGE_B);

    // per-lane ldsm addressing (validated mapping)
    const uint32_t aRow = (uint32_t)(wm * 64 + (lane & 15));
    const uint32_t aCb  = (uint32_t)((lane >> 4) << 4);
    const uint32_t bRow = (uint32_t)(wn * 32 + ((lane >> 4) << 3) + (lane & 7));
    const uint32_t bCb  = (uint32_t)(((lane >> 3) & 1) << 4);

#pragma unroll 1
    for (int i = 0; i < NCHUNK; ++i) {
        if (i + 1 < NCHUNK) { CP_WAIT(1); } else { CP_WAIT(0); }
        __syncthreads();

        if (i + 2 < NCHUNK)
            load_chunk((i + 2) * BKC, base + ((i + 2) % NSTAGE) * STAGE_B);

        const uint32_t stg = base + (i % NSTAGE) * STAGE_B;
        const uint32_t sA0 = stg;
        const uint32_t sA1 = stg + 1 * TILE_B;
        const uint32_t sB0 = stg + 2 * TILE_B;
        const uint32_t sB1 = stg + 3 * TILE_B;

#pragma unroll
        for (int kk = 0; kk < 4; ++kk) {           // 4 x k32 = 128
            uint32_t b0[4][2], b1[4][2];
#pragma unroll
            for (int j = 0; j < 2; ++j) {
                const uint32_t off = sw128((bRow + j * 16) * 128 + kk * 32 + bCb);
                uint32_t t[4];
                ldsm4(t, sB0 + off);
                b0[j*2][0] = t[0]; b0[j*2][1] = t[1];
                b0[j*2+1][0] = t[2]; b0[j*2+1][1] = t[3];
                ldsm4(t, sB1 + off);
                b1[j*2][0] = t[0]; b1[j*2][1] = t[1];
                b1[j*2+1][0] = t[2]; b1[j*2+1][1] = t[3];
            }
            // Per mt: a0 products first (a0 dies), then a1 products.
#pragma unroll
            for (int mt = 0; mt < 4; ++mt) {
                const uint32_t offA = sw128((aRow + mt * 16) * 128 + kk * 32 + aCb);
                uint32_t a0[4];
                ldsm4(a0, sA0 + offA);
#pragma unroll
                for (int nt = 0; nt < 4; ++nt) imma_ss(acc0[mt][nt], a0, b0[nt]);
#pragma unroll
                for (int nt = 0; nt < 4; ++nt) imma_su(accm[mt][nt], a0, b1[nt]);
                uint32_t a1[4];
                ldsm4(a1, sA1 + offA);
#pragma unroll
                for (int nt = 0; nt < 4; ++nt) imma_us(accm[mt][nt], a1, b0[nt]);
#pragma unroll
                for (int nt = 0; nt < 4; ++nt) imma_uu(acc1[mt][nt], a1, b1[nt]);
            }
        }
    }

    // ---- Epilogue: exact recombination + scales + bias ----
    const int l4 = lane >> 2;
    const int l2 = (lane & 3) * 2;
#pragma unroll
    for (int mt = 0; mt < 4; ++mt) {
#pragma unroll
        for (int half = 0; half < 2; ++half) {
            const int r = rowBase + wm * 64 + mt * 16 + l4 + half * 8;
            const float sa = __ldg(&scA[z * sScA + r]);
            float rbias = 0.f;
            if (BIAS_MODE == 2) rbias = __ldg(&bias[r]);
#pragma unroll
            for (int nt = 0; nt < 4; ++nt) {
                const int c = colBase + wn * 32 + nt * 8 + l2;
                const size_t i0 = (size_t)z * sScB + (size_t)c * ldScB;
                const float p0 = sa * __ldg(&scB[i0]);
                const float p1 = sa * __ldg(&scB[i0 + ldScB]);
                const int e = half * 2;
                float s0 = fmaf(65536.f, (float)acc0[mt][nt][e + 0],
                           fmaf(256.f,   (float)accm[mt][nt][e + 0],
                                         (float)acc1[mt][nt][e + 0]));
                float s1 = fmaf(65536.f, (float)acc0[mt][nt][e + 1],
                           fmaf(256.f,   (float)accm[mt][nt][e + 1],
                                         (float)acc1[mt][nt][e + 1]));
                float v0 = p0 * s0;
                float v1 = p1 * s1;
                if (BIAS_MODE == 1) {
                    float2 bv = *reinterpret_cast<const float2*>(&bias[c]);
                    v0 += bv.x; v1 += bv.y;
                } else if (BIAS_MODE == 2) {
                    v0 += rbias; v1 += rbias;
                }
                float2 st; st.x = v0; st.y = v1;
                *reinterpret_cast<float2*>(C + (size_t)z * strC + (size_t)r * ldc + c) = st;
            }
        }
    }
}

// ============================================================================
// Softmax over 1024-wide rows; fp32 scores in, quantized P out.
//   p_i = e_i/tot, rowmax(p) = 1/tot  =>  x16 = round(e_i * 32512) exactly.
// ============================================================================
__global__ void __launch_bounds__(256)
softmax_quant(const float* __restrict__ S, int8_t* __restrict__ A0,
              uint8_t* __restrict__ A1, float* __restrict__ sc)
{
    const int row = blockIdx.x;
    const int t = threadIdx.x;
    const int w = t >> 5, l = t & 31;
    __shared__ float red[8];

    float4 v = *reinterpret_cast<const float4*>(S + (size_t)row * 1024 + t * 4);

    float m = fmaxf(fmaxf(v.x, v.y), fmaxf(v.z, v.w));
#pragma unroll
    for (int o = 16; o; o >>= 1) m = fmaxf(m, __shfl_xor_sync(0xffffffffu, m, o));
    if (l == 0) red[w] = m;
    __syncthreads();
    float rm = fmaxf(fmaxf(fmaxf(red[0], red[1]), fmaxf(red[2], red[3])),
                     fmaxf(fmaxf(red[4], red[5]), fmaxf(red[6], red[7])));

    v.x = __expf(v.x - rm);
    v.y = __expf(v.y - rm);
    v.z = __expf(v.z - rm);
    v.w = __expf(v.w - rm);

    float s = v.x + v.y + v.z + v.w;
#pragma unroll
    for (int o = 16; o; o >>= 1) s += __shfl_xor_sync(0xffffffffu, s, o);
    __syncthreads();
    if (l == 0) red[w] = s;
    __syncthreads();
    float tot = (red[0] + red[1]) + (red[2] + red[3])
              + (red[4] + red[5]) + (red[6] + red[7]);

    int x0 = __float2int_rn(v.x * 32512.0f);
    int x1 = __float2int_rn(v.y * 32512.0f);
    int x2 = __float2int_rn(v.z * 32512.0f);
    int x3 = __float2int_rn(v.w * 32512.0f);

    uchar4 hi = make_uchar4((uint8_t)(int8_t)(x0 >> 8), (uint8_t)(int8_t)(x1 >> 8),
                            (uint8_t)(int8_t)(x2 >> 8), (uint8_t)(int8_t)(x3 >> 8));
    uchar4 lo = make_uchar4((uint8_t)(x0 & 255), (uint8_t)(x1 & 255),
                            (uint8_t)(x2 & 255), (uint8_t)(x3 & 255));
    *reinterpret_cast<uchar4*>(A0 + (size_t)row * 1024 + t * 4) = hi;
    *reinterpret_cast<uchar4*>(A1 + (size_t)row * 1024 + t * 4) = lo;

    if (t == 0) sc[row] = 1.0f / (32512.0f * tot);
}

// ============================================================================
// kernel_launch
// ============================================================================
extern "C" void kernel_launch(void* const* d_in, const int* in_sizes, int n_in,
                              void* d_out, int out_size)
{
    const float* meme  = (const float*)d_in[0];
    const float* text  = (const float*)d_in[1];
    const float* emoji = (const float*)d_in[2];
    const float* Wq    = (const float*)d_in[3];
    const float* bq    = (const float*)d_in[4];
    const float* Wk    = (const float*)d_in[5];
    const float* bk    = (const float*)d_in[6];
    const float* Wv    = (const float*)d_in[7];
    const float* bv    = (const float*)d_in[8];
    float* out = (float*)d_out;

    int8_t  *Xa0, *Wa0, *Qa0, *Ka0, *Va0, *Pa0;
    uint8_t *Xa1, *Wa1, *Qa1, *Ka1, *Va1, *Pa1;
    float *Xsc, *Wsc, *Qsc, *Ksc, *Vsc, *Psc, *F;
    cudaGetSymbolAddress((void**)&Xa0, g_Xa0); cudaGetSymbolAddress((void**)&Xa1, g_Xa1);
    cudaGetSymbolAddress((void**)&Xsc, g_Xsc);
    cudaGetSymbolAddress((void**)&Wa0, g_Wa0); cudaGetSymbolAddress((void**)&Wa1, g_Wa1);
    cudaGetSymbolAddress((void**)&Wsc, g_Wsc);
    cudaGetSymbolAddress((void**)&Qa0, g_Qa0); cudaGetSymbolAddress((void**)&Qa1, g_Qa1);
    cudaGetSymbolAddress((void**)&Qsc, g_Qsc);
    cudaGetSymbolAddress((void**)&Ka0, g_Ka0); cudaGetSymbolAddress((void**)&Ka1, g_Ka1);
    cudaGetSymbolAddress((void**)&Ksc, g_Ksc);
    cudaGetSymbolAddress((void**)&Va0, g_Va0); cudaGetSymbolAddress((void**)&Va1, g_Va1);
    cudaGetSymbolAddress((void**)&Vsc, g_Vsc);
    cudaGetSymbolAddress((void**)&Pa0, g_Pa0); cudaGetSymbolAddress((void**)&Pa1, g_Pa1);
    cudaGetSymbolAddress((void**)&Psc, g_Psc);
    cudaGetSymbolAddress((void**)&F, g_F);

    cudaFuncSetAttribute(gemm_i8<0>, cudaFuncAttributeMaxDynamicSharedMemorySize, GEMM_SMEM);
    cudaFuncSetAttribute(gemm_i8<1>, cudaFuncAttributeMaxDynamicSharedMemorySize, GEMM_SMEM);
    cudaFuncSetAttribute(gemm_i8<2>, cudaFuncAttributeMaxDynamicSharedMemorySize, GEMM_SMEM);

    const size_t bstr = (size_t)SEQ * HID;          // 1M elems per batch
    dim3 blk(256);
    dim3 gProj(HID / 128, MTOT / 128, 1);           // (8, 128)
    dim3 gVT(MTOT / 128, HID / 128, 1);             // (128, 8)
    dim3 gAtt(SEQ / 128, SEQ / 128, NBAT);          // (8, 8, 16)

    // ---- Q projection: Qf = meme . Wq^T + bq ----
    quant_rows<<<MTOT, blk>>>(meme, Xa0, Xa1, Xsc);
    quant_rows<<<HID, blk>>>(Wq, Wa0, Wa1, Wsc);
    gemm_i8<1><<<gProj, blk, GEMM_SMEM>>>(Xa0, Xa1, Xsc, KD, 0, 0,
                                          Wa0, Wa1, Wsc, KD, 0, 0, 1,
                                          bq, F, HID, 0);
    quant_rows<<<MTOT, blk>>>(F, Qa0, Qa1, Qsc);

    // ---- K projection ----
    quant_rows<<<MTOT, blk>>>(text, Xa0, Xa1, Xsc);
    quant_rows<<<HID, blk>>>(Wk, Wa0, Wa1, Wsc);
    gemm_i8<1><<<gProj, blk, GEMM_SMEM>>>(Xa0, Xa1, Xsc, KD, 0, 0,
                                          Wa0, Wa1, Wsc, KD, 0, 0, 1,
                                          bk, F, HID, 0);
    quant_rows<<<MTOT, blk>>>(F, Ka0, Ka1, Ksc);

    // ---- V^T projection: VTf[a][l_glob] = Wv[a][:] . emoji[l_glob][:] + bv[a] ----
    quant_rows<<<MTOT, blk>>>(emoji, Xa0, Xa1, Xsc);
    quant_rows<<<HID, blk>>>(Wv, Wa0, Wa1, Wsc);
    gemm_i8<2><<<gVT, blk, GEMM_SMEM>>>(Wa0, Wa1, Wsc, KD, 0, 0,
                                        Xa0, Xa1, Xsc, KD, 0, 0, 1,
                                        bv, F, MTOT, 0);
    // quantize VT per (a,z) 1024-segment (segments contiguous in F)
    quant_rows<<<MTOT, blk>>>(F, Va0, Va1, Vsc);

    // ---- Scores: S = Q . K^T per batch ----
    gemm_i8<0><<<gAtt, blk, GEMM_SMEM>>>(Qa0, Qa1, Qsc, KD, bstr, SEQ,
                                         Ka0, Ka1, Ksc, KD, bstr, SEQ, 1,
                                         nullptr, F, SEQ, bstr);
    // ---- Softmax -> quantized P ----
    softmax_quant<<<MTOT, blk>>>(F, Pa0, Pa1, Psc);

    // ---- Output: out[q][a] = P[q][:] . VT-seg(a, z)[:] ----
    // B row n=a within batch z lives at row a, offset z*1024: ldb=16384, strB=1024.
    gemm_i8<0><<<gAtt, blk, GEMM_SMEM>>>(Pa0, Pa1, Psc, KD, bstr, SEQ,
                                         Va0, Va1, Vsc, MTOT, KD, 1, NBAT,
                                         nullptr, out, HID, bstr);
}

// round 8
// speedup vs baseline: 3.8151x; 3.8151x over previous
#include <cuda_runtime.h>
#include <cuda_bf16.h>
#include <cstdint>

// Problem dims (fixed)
#define HID   1024
#define NBAT  16
#define SEQ   1024
#define MTOT  (NBAT * SEQ)        // 16384

// ============================================================================
// PTX helpers available on base sm_103 target
// ============================================================================
__device__ __forceinline__ uint32_t smem_u32_of(const void* p) {
    uint32_t a;
    asm("{ .reg .u64 t; cvta.to.shared.u64 t, %1; cvt.u32.u64 %0, t; }"
        : "=r"(a) : "l"(p));
    return a;
}

__device__ __forceinline__ void cp16(uint32_t s, const void* g) {
    asm volatile("cp.async.cg.shared.global [%0], [%1], 16;" :: "r"(s), "l"(g));
}
#define CP_COMMIT() asm volatile("cp.async.commit_group;" ::: "memory")
#define CP_WAIT(N)  asm volatile("cp.async.wait_group %0;" :: "n"(N) : "memory")

__device__ __forceinline__ void ldsm4(uint32_t* r, uint32_t addr) {
    asm volatile("ldmatrix.sync.aligned.m8n8.x4.shared.b16 {%0,%1,%2,%3}, [%4];"
        : "=r"(r[0]), "=r"(r[1]), "=r"(r[2]), "=r"(r[3]) : "r"(addr));
}

__device__ __forceinline__ void mma_bf16(float* c, const uint32_t* a, const uint32_t* b) {
    asm volatile(
        "mma.sync.aligned.m16n8k16.row.col.f32.bf16.bf16.f32 "
        "{%0,%1,%2,%3}, {%4,%5,%6,%7}, {%8,%9}, {%0,%1,%2,%3};"
        : "+f"(c[0]), "+f"(c[1]), "+f"(c[2]), "+f"(c[3])
        : "r"(a[0]), "r"(a[1]), "r"(a[2]), "r"(a[3]), "r"(b[0]), "r"(b[1]));
}

// Conflict-free swizzle for 64-byte smem rows:
// XOR 16B-column bits [5:4] with row bits [8:7]; per 8-row ldmatrix phase the
// bank-group map g=(4r + j^((r>>1)&3)) mod 8 is a permutation.
__device__ __forceinline__ uint32_t sw64(uint32_t o) { return o ^ ((o >> 3) & 0x30); }

// ============================================================================
// Device global scratch (bf16 hi/lo intermediates)
// ============================================================================
__device__ __align__(16) __nv_bfloat16 g_Xh[MTOT * HID];
__device__ __align__(16) __nv_bfloat16 g_Xl[MTOT * HID];
__device__ __align__(16) __nv_bfloat16 g_Wh[HID * HID];
__device__ __align__(16) __nv_bfloat16 g_Wl[HID * HID];
__device__ __align__(16) __nv_bfloat16 g_Qh[MTOT * HID];
__device__ __align__(16) __nv_bfloat16 g_Ql[MTOT * HID];
__device__ __align__(16) __nv_bfloat16 g_Kh[MTOT * HID];
__device__ __align__(16) __nv_bfloat16 g_Kl[MTOT * HID];
__device__ __align__(16) __nv_bfloat16 g_VTh[MTOT * HID];  // [a][b*1024+l], ld=16384
__device__ __align__(16) __nv_bfloat16 g_VTl[MTOT * HID];
__device__ __align__(16) float         g_S [MTOT * SEQ];   // scores fp32
__device__ __align__(16) __nv_bfloat16 g_Ph[MTOT * SEQ];
__device__ __align__(16) __nv_bfloat16 g_Pl[MTOT * SEQ];

// ============================================================================
// fp32 -> (bf16 hi, bf16 lo) elementwise split
// ============================================================================
__global__ void __launch_bounds__(256)
f32_to_split(const float* __restrict__ x, __nv_bfloat16* __restrict__ h,
             __nv_bfloat16* __restrict__ l, int n4)
{
    int i = blockIdx.x * blockDim.x + threadIdx.x;
    if (i >= n4) return;
    float4 v = reinterpret_cast<const float4*>(x)[i];
    __nv_bfloat16 h0 = __float2bfloat16(v.x);
    __nv_bfloat16 h1 = __float2bfloat16(v.y);
    __nv_bfloat16 h2 = __float2bfloat16(v.z);
    __nv_bfloat16 h3 = __float2bfloat16(v.w);
    __nv_bfloat16 l0 = __float2bfloat16(v.x - __bfloat162float(h0));
    __nv_bfloat16 l1 = __float2bfloat16(v.y - __bfloat162float(h1));
    __nv_bfloat16 l2 = __float2bfloat16(v.z - __bfloat162float(h2));
    __nv_bfloat16 l3 = __float2bfloat16(v.w - __bfloat162float(h3));
    reinterpret_cast<__nv_bfloat162*>(h)[2 * i + 0] = __halves2bfloat162(h0, h1);
    reinterpret_cast<__nv_bfloat162*>(h)[2 * i + 1] = __halves2bfloat162(h2, h3);
    reinterpret_cast<__nv_bfloat162*>(l)[2 * i + 0] = __halves2bfloat162(l0, l1);
    reinterpret_cast<__nv_bfloat162*>(l)[2 * i + 1] = __halves2bfloat162(l2, l3);
}

// ============================================================================
// Split-bf16 NT GEMM on mma.sync (HMMA), occupancy-2 version:
//   D[m][n] = sum_k A[m][k]*B[n][k]  (hi*hi + hi*lo + lo*hi, fp32 accum)
//   CTA 128x128, K=1024, BK=32 (64B rows, sw64), 3-stage cp.async, 2 CTAs/SM.
//   8 warps (2M x 4N), warp tile 64x32, m16n8k16 grid 4x4 per product.
//   BIAS_MODE: 0 none, 1 per-col bias[n], 2 per-row bias[m]
//   OUT_SPLIT: 0 -> fp32 Cf;  1 -> bf16 pair (Ch, Cl)
// ============================================================================
#define KDEPTH   1024
#define BKC      32
#define NCHUNK   (KDEPTH / BKC)     // 32
#define ROWB     64                 // bytes per smem row
#define TILE_B   8192               // 128 rows x 64 B
#define STAGE_B  (4 * TILE_B)       // Ah, Al, Bh, Bl = 32 KB
#define NSTAGE   3
#define GEMM_SMEM (1024 + NSTAGE * STAGE_B)   // ~97 KB -> 2 CTAs/SM

template<int BIAS_MODE, int OUT_SPLIT>
__global__ void __launch_bounds__(256, 2)
gemm_split(const __nv_bfloat16* __restrict__ Ah, const __nv_bfloat16* __restrict__ Al,
           int lda, size_t sA,
           const __nv_bfloat16* __restrict__ Bh, const __nv_bfloat16* __restrict__ Bl,
           int ldb, size_t sB,
           const float* __restrict__ bias,
           float* __restrict__ Cf, __nv_bfloat16* __restrict__ Ch,
           __nv_bfloat16* __restrict__ Cl,
           int ldc, size_t sC)
{
    extern __shared__ char smem[];
    const int tid  = threadIdx.x;
    const int wid  = tid >> 5;
    const int lane = tid & 31;
    const int wm   = wid >> 2;     // 0..1  (M)
    const int wn   = wid & 3;      // 0..3  (N)
    const int z    = blockIdx.z;

    Ah += (size_t)z * sA;  Al += (size_t)z * sA;
    Bh += (size_t)z * sB;  Bl += (size_t)z * sB;
    if (OUT_SPLIT) { Ch += (size_t)z * sC; Cl += (size_t)z * sC; }
    else           { Cf += (size_t)z * sC; }

    const int rowBase = blockIdx.y * 128;
    const int colBase = blockIdx.x * 128;

    const uint32_t raw  = smem_u32_of(smem);
    const uint32_t base = (raw + 1023u) & ~1023u;

    const __nv_bfloat16* aAh = Ah + (size_t)rowBase * lda;
    const __nv_bfloat16* aAl = Al + (size_t)rowBase * lda;
    const __nv_bfloat16* aBh = Bh + (size_t)colBase * ldb;
    const __nv_bfloat16* aBl = Bl + (size_t)colBase * ldb;

    // ---- async chunk loader: 4 tiles of 128 rows x 32 bf16 (64B), sw64 ----
    auto load_chunk = [&](int k0, uint32_t stg) {
#pragma unroll
        for (int it = 0; it < 2; ++it) {
            const int slot = tid + it * 256;     // 0..511
            const int r    = slot >> 2;          // 0..127
            const int seg  = slot & 3;           // 16B segment
            const uint32_t so = sw64((uint32_t)(r * ROWB + seg * 16));
            const size_t ga = (size_t)r * lda + k0 + seg * 8;
            const size_t gb = (size_t)r * ldb + k0 + seg * 8;
            cp16(stg + 0 * TILE_B + so, aAh + ga);
            cp16(stg + 1 * TILE_B + so, aAl + ga);
            cp16(stg + 2 * TILE_B + so, aBh + gb);
            cp16(stg + 3 * TILE_B + so, aBl + gb);
        }
        CP_COMMIT();
    };

    float acc[4][4][4];
#pragma unroll
    for (int mt = 0; mt < 4; ++mt)
#pragma unroll
        for (int nt = 0; nt < 4; ++nt)
#pragma unroll
            for (int e = 0; e < 4; ++e) acc[mt][nt][e] = 0.f;

    // Prologue: chunks 0 and 1
    load_chunk(0, base + 0 * STAGE_B);
    load_chunk(BKC, base + 1 * STAGE_B);

    // Per-lane intra-tile offsets (validated fragment mapping, 64B rows)
    const uint32_t aRow = (uint32_t)(wm * 64 + (lane & 15));                 // + mt*16
    const uint32_t aCb  = (uint32_t)((lane >> 4) << 4);                      // + kk*32
    const uint32_t bRow = (uint32_t)(wn * 32 + ((lane >> 4) << 3) + (lane & 7)); // + j*16
    const uint32_t bCb  = (uint32_t)(((lane >> 3) & 1) << 4);                // + kk*32

#pragma unroll 1
    for (int i = 0; i < NCHUNK; ++i) {
        if (i + 1 < NCHUNK) { CP_WAIT(1); } else { CP_WAIT(0); }
        __syncthreads();

        if (i + 2 < NCHUNK)
            load_chunk((i + 2) * BKC, base + ((i + 2) % NSTAGE) * STAGE_B);

        const uint32_t stg = base + (i % NSTAGE) * STAGE_B;
        const uint32_t sAh = stg;
        const uint32_t sAl = stg + 1 * TILE_B;
        const uint32_t sBh = stg + 2 * TILE_B;
        const uint32_t sBl = stg + 3 * TILE_B;

#pragma unroll
        for (int kk = 0; kk < 2; ++kk) {          // 2 x k16 = 32
            uint32_t bh[4][2], bl[4][2];
#pragma unroll
            for (int j = 0; j < 2; ++j) {
                const uint32_t off = sw64((bRow + j * 16) * ROWB + kk * 32 + bCb);
                uint32_t t[4];
                ldsm4(t, sBh + off);
                bh[j*2][0] = t[0]; bh[j*2][1] = t[1];
                bh[j*2+1][0] = t[2]; bh[j*2+1][1] = t[3];
                ldsm4(t, sBl + off);
                bl[j*2][0] = t[0]; bl[j*2][1] = t[1];
                bl[j*2+1][0] = t[2]; bl[j*2+1][1] = t[3];
            }
            // Per mt: ah products (ah dies), then al products -> low reg pressure
#pragma unroll
            for (int mt = 0; mt < 4; ++mt) {
                const uint32_t offA = sw64((aRow + mt * 16) * ROWB + kk * 32 + aCb);
                uint32_t ah[4];
                ldsm4(ah, sAh + offA);
#pragma unroll
                for (int nt = 0; nt < 4; ++nt) mma_bf16(acc[mt][nt], ah, bh[nt]);
#pragma unroll
                for (int nt = 0; nt < 4; ++nt) mma_bf16(acc[mt][nt], ah, bl[nt]);
                uint32_t al[4];
                ldsm4(al, sAl + offA);
#pragma unroll
                for (int nt = 0; nt < 4; ++nt) mma_bf16(acc[mt][nt], al, bh[nt]);
            }
        }
    }

    // ---- Epilogue: registers -> global ----
    const int l4 = lane >> 2;
    const int l2 = (lane & 3) * 2;
#pragma unroll
    for (int mt = 0; mt < 4; ++mt) {
#pragma unroll
        for (int half = 0; half < 2; ++half) {
            const int r = rowBase + wm * 64 + mt * 16 + l4 + half * 8;
            float rbias = 0.f;
            if (BIAS_MODE == 2) rbias = __ldg(&bias[r]);
#pragma unroll
            for (int nt = 0; nt < 4; ++nt) {
                const int c = colBase + wn * 32 + nt * 8 + l2;
                float v0 = acc[mt][nt][half * 2 + 0];
                float v1 = acc[mt][nt][half * 2 + 1];
                if (BIAS_MODE == 1) {
                    float2 bv = *reinterpret_cast<const float2*>(&bias[c]);
                    v0 += bv.x; v1 += bv.y;
                } else if (BIAS_MODE == 2) {
                    v0 += rbias; v1 += rbias;
                }
                if (OUT_SPLIT == 0) {
                    float2 st; st.x = v0; st.y = v1;
                    *reinterpret_cast<float2*>(Cf + (size_t)r * ldc + c) = st;
                } else {
                    __nv_bfloat16 h0 = __float2bfloat16(v0);
                    __nv_bfloat16 h1 = __float2bfloat16(v1);
                    __nv_bfloat16 q0 = __float2bfloat16(v0 - __bfloat162float(h0));
                    __nv_bfloat16 q1 = __float2bfloat16(v1 - __bfloat162float(h1));
                    *reinterpret_cast<__nv_bfloat162*>(Ch + (size_t)r * ldc + c) =
                        __halves2bfloat162(h0, h1);
                    *reinterpret_cast<__nv_bfloat162*>(Cl + (size_t)r * ldc + c) =
                        __halves2bfloat162(q0, q1);
                }
            }
        }
    }
}

// ============================================================================
// Row softmax over 1024-wide rows; fp32 in, bf16 hi/lo split out.
// ============================================================================
__global__ void __launch_bounds__(256)
softmax_split(const float* __restrict__ S, __nv_bfloat16* __restrict__ Ph,
              __nv_bfloat16* __restrict__ Pl)
{
    const int row = blockIdx.x;
    const int t = threadIdx.x;
    const int w = t >> 5, l = t & 31;

    float4 v = *reinterpret_cast<const float4*>(S + (size_t)row * 1024 + t * 4);

    float m = fmaxf(fmaxf(v.x, v.y), fmaxf(v.z, v.w));
#pragma unroll
    for (int o = 16; o; o >>= 1) m = fmaxf(m, __shfl_xor_sync(0xffffffffu, m, o));

    __shared__ float redm[8], reds[8];
    if (l == 0) redm[w] = m;
    __syncthreads();
    float rm = fmaxf(fmaxf(fmaxf(redm[0], redm[1]), fmaxf(redm[2], redm[3])),
                     fmaxf(fmaxf(redm[4], redm[5]), fmaxf(redm[6], redm[7])));

    v.x = __expf(v.x - rm);
    v.y = __expf(v.y - rm);
    v.z = __expf(v.z - rm);
    v.w = __expf(v.w - rm);

    float s = v.x + v.y + v.z + v.w;
#pragma unroll
    for (int o = 16; o; o >>= 1) s += __shfl_xor_sync(0xffffffffu, s, o);
    if (l == 0) reds[w] = s;
    __syncthreads();
    float tot = (reds[0] + reds[1]) + (reds[2] + reds[3])
              + (reds[4] + reds[5]) + (reds[6] + reds[7]);

    const float inv = 1.0f / tot;
    float w0 = v.x * inv, w1 = v.y * inv, w2 = v.z * inv, w3 = v.w * inv;

    __nv_bfloat16 h0 = __float2bfloat16(w0), h1 = __float2bfloat16(w1);
    __nv_bfloat16 h2 = __float2bfloat16(w2), h3 = __float2bfloat16(w3);
    __nv_bfloat16 l0 = __float2bfloat16(w0 - __bfloat162float(h0));
    __nv_bfloat16 l1 = __float2bfloat16(w1 - __bfloat162float(h1));
    __nv_bfloat16 l2 = __float2bfloat16(w2 - __bfloat162float(h2));
    __nv_bfloat16 l3 = __float2bfloat16(w3 - __bfloat162float(h3));

    const size_t p2 = ((size_t)row * 1024 + t * 4) >> 1;
    reinterpret_cast<__nv_bfloat162*>(Ph)[p2 + 0] = __halves2bfloat162(h0, h1);
    reinterpret_cast<__nv_bfloat162*>(Ph)[p2 + 1] = __halves2bfloat162(h2, h3);
    reinterpret_cast<__nv_bfloat162*>(Pl)[p2 + 0] = __halves2bfloat162(l0, l1);
    reinterpret_cast<__nv_bfloat162*>(Pl)[p2 + 1] = __halves2bfloat162(l2, l3);
}

// ============================================================================
// kernel_launch
// ============================================================================
extern "C" void kernel_launch(void* const* d_in, const int* in_sizes, int n_in,
                              void* d_out, int out_size)
{
    const float* meme  = (const float*)d_in[0];
    const float* text  = (const float*)d_in[1];
    const float* emoji = (const float*)d_in[2];
    const float* Wq    = (const float*)d_in[3];
    const float* bq    = (const float*)d_in[4];
    const float* Wk    = (const float*)d_in[5];
    const float* bk    = (const float*)d_in[6];
    const float* Wv    = (const float*)d_in[7];
    const float* bv    = (const float*)d_in[8];
    float* out = (float*)d_out;

    __nv_bfloat16 *Xh, *Xl, *Wh, *Wl, *Qh, *Ql, *Kh, *Kl, *VTh, *VTl, *Ph, *Pl;
    float* S;
    cudaGetSymbolAddress((void**)&Xh, g_Xh);   cudaGetSymbolAddress((void**)&Xl, g_Xl);
    cudaGetSymbolAddress((void**)&Wh, g_Wh);   cudaGetSymbolAddress((void**)&Wl, g_Wl);
    cudaGetSymbolAddress((void**)&Qh, g_Qh);   cudaGetSymbolAddress((void**)&Ql, g_Ql);
    cudaGetSymbolAddress((void**)&Kh, g_Kh);   cudaGetSymbolAddress((void**)&Kl, g_Kl);
    cudaGetSymbolAddress((void**)&VTh, g_VTh); cudaGetSymbolAddress((void**)&VTl, g_VTl);
    cudaGetSymbolAddress((void**)&Ph, g_Ph);   cudaGetSymbolAddress((void**)&Pl, g_Pl);
    cudaGetSymbolAddress((void**)&S, g_S);

    cudaFuncSetAttribute(gemm_split<1, 1>, cudaFuncAttributeMaxDynamicSharedMemorySize, GEMM_SMEM);
    cudaFuncSetAttribute(gemm_split<2, 1>, cudaFuncAttributeMaxDynamicSharedMemorySize, GEMM_SMEM);
    cudaFuncSetAttribute(gemm_split<0, 0>, cudaFuncAttributeMaxDynamicSharedMemorySize, GEMM_SMEM);

    const size_t bstr = (size_t)SEQ * HID;          // 1M elems per batch
    const int nx4 = (MTOT * HID) / 4;
    const int nw4 = (HID * HID) / 4;

    dim3 blk(256);
    dim3 gProj(HID / 128, MTOT / 128, 1);           // (8, 128)
    dim3 gVT(MTOT / 128, HID / 128, 1);             // (128, 8)
    dim3 gAtt(SEQ / 128, SEQ / 128, NBAT);          // (8, 8, 16)

    // Q projection: Q[l][a] = meme[l][:] . Wq[a][:] + bq[a]
    f32_to_split<<<(nx4 + 255) / 256, blk>>>(meme, Xh, Xl, nx4);
    f32_to_split<<<(nw4 + 255) / 256, blk>>>(Wq, Wh, Wl, nw4);
    gemm_split<1, 1><<<gProj, blk, GEMM_SMEM>>>(Xh, Xl, HID, 0, Wh, Wl, HID, 0,
                                                bq, nullptr, Qh, Ql, HID, 0);
    // K projection
    f32_to_split<<<(nx4 + 255) / 256, blk>>>(text, Xh, Xl, nx4);
    f32_to_split<<<(nw4 + 255) / 256, blk>>>(Wk, Wh, Wl, nw4);
    gemm_split<1, 1><<<gProj, blk, GEMM_SMEM>>>(Xh, Xl, HID, 0, Wh, Wl, HID, 0,
                                                bk, nullptr, Kh, Kl, HID, 0);
    // V^T projection: VT[a][lg] = Wv[a][:] . emoji[lg][:] + bv[a]  (ldc = 16384)
    f32_to_split<<<(nx4 + 255) / 256, blk>>>(emoji, Xh, Xl, nx4);
    f32_to_split<<<(nw4 + 255) / 256, blk>>>(Wv, Wh, Wl, nw4);
    gemm_split<2, 1><<<gVT, blk, GEMM_SMEM>>>(Wh, Wl, HID, 0, Xh, Xl, HID, 0,
                                              bv, nullptr, VTh, VTl, MTOT, 0);
    // Scores: per batch  S[q][k] = Q[q][:] . K[k][:]
    gemm_split<0, 0><<<gAtt, blk, GEMM_SMEM>>>(Qh, Ql, HID, bstr, Kh, Kl, HID, bstr,
                                               nullptr, S, nullptr, nullptr, SEQ, bstr);
    // Softmax -> split weights
    softmax_split<<<MTOT, blk>>>(S, Ph, Pl);
    // Output: per batch  O[q][a] = P[q][:] . VT[a][b*1024 + :]
    gemm_split<0, 0><<<gAtt, blk, GEMM_SMEM>>>(Ph, Pl, SEQ, bstr,
                                               VTh, VTl, MTOT, (size_t)SEQ,
                                               nullptr, out, nullptr, nullptr, HID, bstr);
}